// round 15
// baseline (speedup 1.0000x reference)
#include <cuda_runtime.h>

#define NN   100000
#define NE   1250000
#define FEATD 64
#define HIDD  10
#define PADD  12          // fp32 agg rows: 12 floats (48B, 16B-aligned)
#define INV_MOD 0.1f
#define FB   128          // nodes per block in final kernel

// Scratch (no cudaMalloc allowed).
__device__ uint4 g_Aq[NN];           // dst-side projection (10x12bit + exp, 16B)
__device__ uint4 g_Bq[NN];           // src-side projection (10x12bit + exp, 16B)
__device__ float g_agg[NN * PADD];   // aggregation buffer (fp32)

__device__ __forceinline__ void fma4(float4& acc, float s, const float4 w) {
    acc.x = fmaf(s, w.x, acc.x);
    acc.y = fmaf(s, w.y, acc.y);
    acc.z = fmaf(s, w.z, acc.z);
    acc.w = fmaf(s, w.w, acc.w);
}

// Packed fp32x2 FMA (FFMA2) — PTX-only on sm_103a.
__device__ __forceinline__ void ffma2(unsigned long long& acc,
                                      unsigned long long a, unsigned long long b) {
    asm("fma.rn.f32x2 %0, %1, %2, %0;" : "+l"(acc) : "l"(a), "l"(b));
}
__device__ __forceinline__ unsigned long long pack2(float lo, float hi) {
    unsigned long long r;
    asm("mov.b64 %0, {%1, %2};" : "=l"(r) : "f"(lo), "f"(hi));
    return r;
}
__device__ __forceinline__ float2 unpack2(unsigned long long v) {
    float lo, hi;
    asm("mov.b64 {%0, %1}, %2;" : "=f"(lo), "=f"(hi) : "l"(v));
    return make_float2(lo, hi);
}

// Pack 10 fp32 into 16B: 10 x 12-bit biased fixed-point + shared exponent byte.
__device__ __forceinline__ void store_q_row(uint4* dst, const float* b) {
    float m = 0.f;
    #pragma unroll
    for (int i = 0; i < 10; i++) m = fmaxf(m, fabsf(b[i]));
    int eb = 0;
    frexpf(m, &eb);
    int ebc = min(max(116 + eb, 1), 254);
    float invstep = __uint_as_float((unsigned)(254 - ebc) << 23);
    unsigned wds[4] = {0u, 0u, 0u, 0u};
    #pragma unroll
    for (int i = 0; i < 10; i++) {
        int q = __float2int_rn(b[i] * invstep);
        q = min(max(q, -2047), 2047);
        unsigned uq = (unsigned)(q + 2048);
        int off = 12 * i, wi = off >> 5, sh = off & 31;
        wds[wi] |= uq << sh;
        if (sh > 20) wds[wi + 1] |= uq >> (32 - sh);
    }
    wds[3] |= (unsigned)ebc << 24;
    *dst = make_uint4(wds[0], wds[1], wds[2], wds[3]);
}

__device__ __forceinline__ void decode_q_row(const uint4 q, float* v) {
    float step = __uint_as_float((q.w >> 24) << 23);
    float bias = -2048.0f * step;
    unsigned wds[4] = {q.x, q.y, q.z, q.w};
    #pragma unroll
    for (int i = 0; i < 10; i++) {
        int off = 12 * i, wi = off >> 5, sh = off & 31;
        unsigned hi = (wi < 3) ? wds[wi + 1] : wds[0];
        unsigned uq = __funnelshift_r(wds[wi], hi, sh) & 0xFFFu;
        v[i] = fmaf((float)uq, step, bias);
    }
}

// ========================= node precompute kernels ==========================

__global__ void __launch_bounds__(128) pre0(const float* __restrict__ X,
                                            const float* __restrict__ W2) {
    __shared__ float sW[128 * PADD];      // [128,10] padded to [128,12]
    for (int i = threadIdx.x; i < 128 * PADD; i += blockDim.x) {
        int f = i / PADD, k = i % PADD;
        sW[i] = (k < HIDD) ? W2[f * HIDD + k] : 0.0f;
    }
    __syncthreads();

    int n = blockIdx.x * blockDim.x + threadIdx.x;
    if (n >= NN) return;

    const float4* xr  = (const float4*)(X + (long)n * FEATD);
    const float4* sW4 = (const float4*)sW;

    float4 a[3], b[3];
    #pragma unroll
    for (int c = 0; c < 3; c++) { a[c] = make_float4(0.f,0.f,0.f,0.f); b[c] = make_float4(0.f,0.f,0.f,0.f); }

    #pragma unroll 4
    for (int f4 = 0; f4 < 16; f4++) {
        float4 x = xr[f4];
        float xs[4] = {x.x, x.y, x.z, x.w};
        #pragma unroll
        for (int q = 0; q < 4; q++) {
            int f = f4 * 4 + q;
            #pragma unroll
            for (int c = 0; c < 3; c++) {
                fma4(a[c], xs[q], sW4[f * 3 + c]);
                fma4(b[c], xs[q], sW4[(FEATD + f) * 3 + c]);
            }
        }
    }

    float aa[10] = {a[0].x,a[0].y,a[0].z,a[0].w,a[1].x,a[1].y,a[1].z,a[1].w,a[2].x,a[2].y};
    float bb[10] = {b[0].x,b[0].y,b[0].z,b[0].w,b[1].x,b[1].y,b[1].z,b[1].w,b[2].x,b[2].y};
    store_q_row(&g_Aq[n], aa);
    store_q_row(&g_Bq[n], bb);

    float4* Gr = (float4*)(g_agg + (long)n * PADD);
    float4 z = make_float4(0.f, 0.f, 0.f, 0.f);
    Gr[0] = z; Gr[1] = z; Gr[2] = z;
}

__global__ void __launch_bounds__(128) pre12(const float* __restrict__ W2) {
    __shared__ float sW[20 * PADD];
    for (int i = threadIdx.x; i < 20 * PADD; i += blockDim.x) {
        int r = i / PADD, k = i % PADD;
        sW[i] = (k < HIDD) ? W2[r * HIDD + k] : 0.0f;
    }
    __syncthreads();

    int n = blockIdx.x * blockDim.x + threadIdx.x;
    if (n >= NN) return;

    float4* Gr = (float4*)(g_agg + (long)n * PADD);
    float4 g0 = Gr[0], g1 = Gr[1], g2 = Gr[2];
    float h[HIDD];
    h[0]=fmaxf(g0.x,0.f); h[1]=fmaxf(g0.y,0.f); h[2]=fmaxf(g0.z,0.f); h[3]=fmaxf(g0.w,0.f);
    h[4]=fmaxf(g1.x,0.f); h[5]=fmaxf(g1.y,0.f); h[6]=fmaxf(g1.z,0.f); h[7]=fmaxf(g1.w,0.f);
    h[8]=fmaxf(g2.x,0.f); h[9]=fmaxf(g2.y,0.f);

    const float4* sW4 = (const float4*)sW;
    float4 a[3], b[3];
    #pragma unroll
    for (int c = 0; c < 3; c++) { a[c] = make_float4(0.f,0.f,0.f,0.f); b[c] = make_float4(0.f,0.f,0.f,0.f); }
    #pragma unroll
    for (int k = 0; k < HIDD; k++) {
        #pragma unroll
        for (int c = 0; c < 3; c++) {
            fma4(a[c], h[k], sW4[k * 3 + c]);
            fma4(b[c], h[k], sW4[(HIDD + k) * 3 + c]);
        }
    }

    float aa[10] = {a[0].x,a[0].y,a[0].z,a[0].w,a[1].x,a[1].y,a[1].z,a[1].w,a[2].x,a[2].y};
    float bb[10] = {b[0].x,b[0].y,b[0].z,b[0].w,b[1].x,b[1].y,b[1].z,b[1].w,b[2].x,b[2].y};
    store_q_row(&g_Aq[n], aa);
    store_q_row(&g_Bq[n], bb);

    float4 z = make_float4(0.f, 0.f, 0.f, 0.f);
    Gr[0] = z; Gr[1] = z; Gr[2] = z;
}

// =============================== edge kernel ================================
// Unsorted edge-parallel (R11). A and B rows each ONE scattered 16B LDG.

__global__ void __launch_bounds__(256) edge_kernel(const int* __restrict__ es,
                                                   const int* __restrict__ ed,
                                                   const float* __restrict__ W1) {
    __shared__ float sW[HIDD * PADD];     // [10,10] padded to [10,12]
    for (int i = threadIdx.x; i < HIDD * PADD; i += blockDim.x) {
        int k = i / PADD, j = i % PADD;
        sW[i] = (j < HIDD) ? W1[k * HIDD + j] : 0.0f;
    }
    __syncthreads();

    int e = blockIdx.x * blockDim.x + threadIdx.x;
    if (e >= NE) return;

    int s = es[e];
    int d = ed[e];

    uint4 aq = __ldg(&g_Aq[d]);
    uint4 bq = __ldg(&g_Bq[s]);

    float av[10], bv[10];
    decode_q_row(aq, av);
    decode_q_row(bq, bv);

    float t[HIDD];
    #pragma unroll
    for (int i = 0; i < 10; i++) t[i] = fmaxf(av[i] + bv[i], 0.f);

    const float4* sW4 = (const float4*)sW;
    float4 u0 = make_float4(0.f,0.f,0.f,0.f);
    float4 u1 = make_float4(0.f,0.f,0.f,0.f);
    float4 u2 = make_float4(0.f,0.f,0.f,0.f);
    #pragma unroll
    for (int k = 0; k < HIDD; k++) {
        float tk = t[k];
        fma4(u0, tk, sW4[k * 3 + 0]);
        fma4(u1, tk, sW4[k * 3 + 1]);
        fma4(u2, tk, sW4[k * 3 + 2]);
    }

    u0.x = fmaxf(u0.x,0.f)*INV_MOD; u0.y = fmaxf(u0.y,0.f)*INV_MOD;
    u0.z = fmaxf(u0.z,0.f)*INV_MOD; u0.w = fmaxf(u0.w,0.f)*INV_MOD;
    u1.x = fmaxf(u1.x,0.f)*INV_MOD; u1.y = fmaxf(u1.y,0.f)*INV_MOD;
    u1.z = fmaxf(u1.z,0.f)*INV_MOD; u1.w = fmaxf(u1.w,0.f)*INV_MOD;
    u2.x = fmaxf(u2.x,0.f)*INV_MOD; u2.y = fmaxf(u2.y,0.f)*INV_MOD;

    float* Gr = g_agg + (long)d * PADD;   // 48B rows -> base 16B-aligned
    asm volatile("red.global.add.v4.f32 [%0], {%1, %2, %3, %4};"
                 :: "l"(Gr), "f"(u0.x), "f"(u0.y), "f"(u0.z), "f"(u0.w) : "memory");
    asm volatile("red.global.add.v4.f32 [%0], {%1, %2, %3, %4};"
                 :: "l"(Gr + 4), "f"(u1.x), "f"(u1.y), "f"(u1.z), "f"(u1.w) : "memory");
    asm volatile("red.global.add.v2.f32 [%0], {%1, %2};"
                 :: "l"(Gr + 8), "f"(u2.x), "f"(u2.y) : "memory");
}

// ============================ fused final head ==============================
// Block-tiled: 128 nodes/block. Phase A stages T (k-major) into smem; phase B
// is a register-tiled GEMM (4 nodes x 8 cols per thread, FFMA2). Per-thread
// smem traffic: 192 LDS.128 instead of 2048 LDS.64.

__global__ void __launch_bounds__(256) final_fused(const float* __restrict__ Wf1,
                                                   const float* __restrict__ Wf2,
                                                   float* __restrict__ out) {
    __shared__ float sW1[HIDD * FEATD];   // 2.5 KB
    __shared__ float sW2[FEATD * FEATD];  // 16 KB, row-major [k][col]
    __shared__ float sT[FEATD * FB];      // 32 KB, k-major [k][node]
    for (int i = threadIdx.x; i < HIDD * FEATD; i += blockDim.x) sW1[i] = Wf1[i];
    for (int i = threadIdx.x; i < FEATD * FEATD; i += blockDim.x) sW2[i] = Wf2[i];
    __syncthreads();

    int n0 = blockIdx.x * FB;

    // ---- Phase A: threads 0..127 each compute one node's T row ----
    if (threadIdx.x < FB) {
        int n = n0 + threadIdx.x;
        float h[HIDD];
        if (n < NN) {
            const float4* Gr = (const float4*)(g_agg + (long)n * PADD);
            float4 g0 = Gr[0], g1 = Gr[1], g2 = Gr[2];
            h[0]=fmaxf(g0.x,0.f); h[1]=fmaxf(g0.y,0.f); h[2]=fmaxf(g0.z,0.f); h[3]=fmaxf(g0.w,0.f);
            h[4]=fmaxf(g1.x,0.f); h[5]=fmaxf(g1.y,0.f); h[6]=fmaxf(g1.z,0.f); h[7]=fmaxf(g1.w,0.f);
            h[8]=fmaxf(g2.x,0.f); h[9]=fmaxf(g2.y,0.f);
        } else {
            #pragma unroll
            for (int i = 0; i < HIDD; i++) h[i] = 0.f;
        }

        const float4* sW1_4 = (const float4*)sW1;
        float4 t[16];
        #pragma unroll
        for (int c = 0; c < 16; c++) t[c] = make_float4(0.f,0.f,0.f,0.f);
        #pragma unroll
        for (int k = 0; k < HIDD; k++) {
            float hk = h[k];
            #pragma unroll
            for (int c = 0; c < 16; c++) fma4(t[c], hk, sW1_4[k * 16 + c]);
        }
        // relu + transpose-store: sT[k][node]  (consecutive lanes -> no conflicts)
        #pragma unroll
        for (int c = 0; c < 16; c++) {
            sT[(4*c+0) * FB + threadIdx.x] = fmaxf(t[c].x, 0.f);
            sT[(4*c+1) * FB + threadIdx.x] = fmaxf(t[c].y, 0.f);
            sT[(4*c+2) * FB + threadIdx.x] = fmaxf(t[c].z, 0.f);
            sT[(4*c+3) * FB + threadIdx.x] = fmaxf(t[c].w, 0.f);
        }
    }
    __syncthreads();

    // ---- Phase B: 256 threads, each 4 nodes x 8 cols ----
    int ng = threadIdx.x >> 3;    // 0..31 node group
    int cg = threadIdx.x & 7;     // 0..7  col group
    int nl = ng * 4;
    int c0 = cg * 8;

    unsigned long long acc[4][4];  // [node][col-pair]
    #pragma unroll
    for (int j = 0; j < 4; j++)
        #pragma unroll
        for (int p = 0; p < 4; p++) acc[j][p] = pack2(0.f, 0.f);

    for (int k = 0; k < FEATD; k++) {
        float4 tn = *(const float4*)&sT[k * FB + nl];          // broadcast within 8 lanes
        const float4* wr = (const float4*)&sW2[k * FEATD + c0]; // 2 x LDS.128, conflict-free
        float4 wa = wr[0], wb = wr[1];
        unsigned long long w0 = pack2(wa.x, wa.y), w1 = pack2(wa.z, wa.w);
        unsigned long long w2 = pack2(wb.x, wb.y), w3 = pack2(wb.z, wb.w);
        float ts[4] = {tn.x, tn.y, tn.z, tn.w};
        #pragma unroll
        for (int j = 0; j < 4; j++) {
            unsigned long long tj = pack2(ts[j], ts[j]);
            ffma2(acc[j][0], tj, w0);
            ffma2(acc[j][1], tj, w1);
            ffma2(acc[j][2], tj, w2);
            ffma2(acc[j][3], tj, w3);
        }
    }

    #pragma unroll
    for (int j = 0; j < 4; j++) {
        int n = n0 + nl + j;
        if (n < NN) {
            float2 p0 = unpack2(acc[j][0]), p1 = unpack2(acc[j][1]);
            float2 p2 = unpack2(acc[j][2]), p3 = unpack2(acc[j][3]);
            float4 v0, v1;
            v0.x = fmaxf(p0.x, 0.f); v0.y = fmaxf(p0.y, 0.f);
            v0.z = fmaxf(p1.x, 0.f); v0.w = fmaxf(p1.y, 0.f);
            v1.x = fmaxf(p2.x, 0.f); v1.y = fmaxf(p2.y, 0.f);
            v1.z = fmaxf(p3.x, 0.f); v1.w = fmaxf(p3.y, 0.f);
            float4* orow = (float4*)(out + (long)n * FEATD + c0);
            orow[0] = v0;
            orow[1] = v1;
        }
    }
}

// ---------------------------------------------------------------------------
// Inputs (metadata order): X, W2_0, W1_0, W2_1, W1_1, W2_2, W1_2, Wf1, Wf2,
//                          edge_src (int32), edge_dst (int32)
// ---------------------------------------------------------------------------
extern "C" void kernel_launch(void* const* d_in, const int* in_sizes, int n_in,
                              void* d_out, int out_size) {
    const float* X    = (const float*)d_in[0];
    const float* W2_0 = (const float*)d_in[1];
    const float* W1_0 = (const float*)d_in[2];
    const float* W2_1 = (const float*)d_in[3];
    const float* W1_1 = (const float*)d_in[4];
    const float* W2_2 = (const float*)d_in[5];
    const float* W1_2 = (const float*)d_in[6];
    const float* Wf1  = (const float*)d_in[7];
    const float* Wf2  = (const float*)d_in[8];
    const int*   es   = (const int*)d_in[9];
    const int*   ed   = (const int*)d_in[10];
    float* out = (float*)d_out;

    const int nodeBlocks = (NN + 127) / 128;
    const int edgeBlocks = (NE + 255) / 256;
    const int finBlocks  = (NN + FB - 1) / FB;

    pre0<<<nodeBlocks, 128>>>(X, W2_0);
    edge_kernel<<<edgeBlocks, 256>>>(es, ed, W1_0);
    pre12<<<nodeBlocks, 128>>>(W2_1);
    edge_kernel<<<edgeBlocks, 256>>>(es, ed, W1_1);
    pre12<<<nodeBlocks, 128>>>(W2_2);
    edge_kernel<<<edgeBlocks, 256>>>(es, ed, W1_2);
    final_fused<<<finBlocks, 256>>>(Wf1, Wf2, out);
}

// round 17
// speedup vs baseline: 1.5611x; 1.5611x over previous
#include <cuda_runtime.h>

#define NN   100000
#define NE   1250000
#define FEATD 64
#define HIDD  10
#define PADD  12          // fp32 agg rows: 12 floats (48B, 16B-aligned)
#define INV_MOD 0.1f
#define FB   128          // nodes per block in final kernel

// Scratch (no cudaMalloc allowed).
__device__ uint4 g_Aq[NN];           // dst-side projection (10x12bit + exp, 16B)
__device__ uint4 g_Bq[NN];           // src-side projection (10x12bit + exp, 16B)
__device__ float g_agg[NN * PADD];   // aggregation buffer (fp32)

__device__ __forceinline__ void fma4(float4& acc, float s, const float4 w) {
    acc.x = fmaf(s, w.x, acc.x);
    acc.y = fmaf(s, w.y, acc.y);
    acc.z = fmaf(s, w.z, acc.z);
    acc.w = fmaf(s, w.w, acc.w);
}

// Packed fp32x2 FMA (FFMA2) — PTX-only on sm_103a.
__device__ __forceinline__ void ffma2(unsigned long long& acc,
                                      unsigned long long a, unsigned long long b) {
    asm("fma.rn.f32x2 %0, %1, %2, %0;" : "+l"(acc) : "l"(a), "l"(b));
}
__device__ __forceinline__ unsigned long long pack2(float lo, float hi) {
    unsigned long long r;
    asm("mov.b64 %0, {%1, %2};" : "=l"(r) : "f"(lo), "f"(hi));
    return r;
}
__device__ __forceinline__ float2 unpack2(unsigned long long v) {
    float lo, hi;
    asm("mov.b64 {%0, %1}, %2;" : "=f"(lo), "=f"(hi) : "l"(v));
    return make_float2(lo, hi);
}

// Pack 10 fp32 into 16B: 10 x 12-bit biased fixed-point + shared exponent byte.
__device__ __forceinline__ void store_q_row(uint4* dst, const float* b) {
    float m = 0.f;
    #pragma unroll
    for (int i = 0; i < 10; i++) m = fmaxf(m, fabsf(b[i]));
    int eb = 0;
    frexpf(m, &eb);
    int ebc = min(max(116 + eb, 1), 254);
    float invstep = __uint_as_float((unsigned)(254 - ebc) << 23);
    unsigned wds[4] = {0u, 0u, 0u, 0u};
    #pragma unroll
    for (int i = 0; i < 10; i++) {
        int q = __float2int_rn(b[i] * invstep);
        q = min(max(q, -2047), 2047);
        unsigned uq = (unsigned)(q + 2048);
        int off = 12 * i, wi = off >> 5, sh = off & 31;
        wds[wi] |= uq << sh;
        if (sh > 20) wds[wi + 1] |= uq >> (32 - sh);
    }
    wds[3] |= (unsigned)ebc << 24;
    *dst = make_uint4(wds[0], wds[1], wds[2], wds[3]);
}

__device__ __forceinline__ void decode_q_row(const uint4 q, float* v) {
    float step = __uint_as_float((q.w >> 24) << 23);
    float bias = -2048.0f * step;
    unsigned wds[4] = {q.x, q.y, q.z, q.w};
    #pragma unroll
    for (int i = 0; i < 10; i++) {
        int off = 12 * i, wi = off >> 5, sh = off & 31;
        unsigned hi = (wi < 3) ? wds[wi + 1] : wds[0];
        unsigned uq = __funnelshift_r(wds[wi], hi, sh) & 0xFFFu;
        v[i] = fmaf((float)uq, step, bias);
    }
}

// ========================= node precompute kernels ==========================

__global__ void __launch_bounds__(128) pre0(const float* __restrict__ X,
                                            const float* __restrict__ W2) {
    __shared__ float sW[128 * PADD];      // [128,10] padded to [128,12]
    for (int i = threadIdx.x; i < 128 * PADD; i += blockDim.x) {
        int f = i / PADD, k = i % PADD;
        sW[i] = (k < HIDD) ? W2[f * HIDD + k] : 0.0f;
    }
    __syncthreads();

    int n = blockIdx.x * blockDim.x + threadIdx.x;
    if (n >= NN) return;

    const float4* xr  = (const float4*)(X + (long)n * FEATD);
    const float4* sW4 = (const float4*)sW;

    float4 a[3], b[3];
    #pragma unroll
    for (int c = 0; c < 3; c++) { a[c] = make_float4(0.f,0.f,0.f,0.f); b[c] = make_float4(0.f,0.f,0.f,0.f); }

    #pragma unroll 4
    for (int f4 = 0; f4 < 16; f4++) {
        float4 x = xr[f4];
        float xs[4] = {x.x, x.y, x.z, x.w};
        #pragma unroll
        for (int q = 0; q < 4; q++) {
            int f = f4 * 4 + q;
            #pragma unroll
            for (int c = 0; c < 3; c++) {
                fma4(a[c], xs[q], sW4[f * 3 + c]);
                fma4(b[c], xs[q], sW4[(FEATD + f) * 3 + c]);
            }
        }
    }

    float aa[10] = {a[0].x,a[0].y,a[0].z,a[0].w,a[1].x,a[1].y,a[1].z,a[1].w,a[2].x,a[2].y};
    float bb[10] = {b[0].x,b[0].y,b[0].z,b[0].w,b[1].x,b[1].y,b[1].z,b[1].w,b[2].x,b[2].y};
    store_q_row(&g_Aq[n], aa);
    store_q_row(&g_Bq[n], bb);

    float4* Gr = (float4*)(g_agg + (long)n * PADD);
    float4 z = make_float4(0.f, 0.f, 0.f, 0.f);
    Gr[0] = z; Gr[1] = z; Gr[2] = z;
}

__global__ void __launch_bounds__(128) pre12(const float* __restrict__ W2) {
    __shared__ float sW[20 * PADD];
    for (int i = threadIdx.x; i < 20 * PADD; i += blockDim.x) {
        int r = i / PADD, k = i % PADD;
        sW[i] = (k < HIDD) ? W2[r * HIDD + k] : 0.0f;
    }
    __syncthreads();

    int n = blockIdx.x * blockDim.x + threadIdx.x;
    if (n >= NN) return;

    float4* Gr = (float4*)(g_agg + (long)n * PADD);
    float4 g0 = Gr[0], g1 = Gr[1], g2 = Gr[2];
    float h[HIDD];
    h[0]=fmaxf(g0.x,0.f); h[1]=fmaxf(g0.y,0.f); h[2]=fmaxf(g0.z,0.f); h[3]=fmaxf(g0.w,0.f);
    h[4]=fmaxf(g1.x,0.f); h[5]=fmaxf(g1.y,0.f); h[6]=fmaxf(g1.z,0.f); h[7]=fmaxf(g1.w,0.f);
    h[8]=fmaxf(g2.x,0.f); h[9]=fmaxf(g2.y,0.f);

    const float4* sW4 = (const float4*)sW;
    float4 a[3], b[3];
    #pragma unroll
    for (int c = 0; c < 3; c++) { a[c] = make_float4(0.f,0.f,0.f,0.f); b[c] = make_float4(0.f,0.f,0.f,0.f); }
    #pragma unroll
    for (int k = 0; k < HIDD; k++) {
        #pragma unroll
        for (int c = 0; c < 3; c++) {
            fma4(a[c], h[k], sW4[k * 3 + c]);
            fma4(b[c], h[k], sW4[(HIDD + k) * 3 + c]);
        }
    }

    float aa[10] = {a[0].x,a[0].y,a[0].z,a[0].w,a[1].x,a[1].y,a[1].z,a[1].w,a[2].x,a[2].y};
    float bb[10] = {b[0].x,b[0].y,b[0].z,b[0].w,b[1].x,b[1].y,b[1].z,b[1].w,b[2].x,b[2].y};
    store_q_row(&g_Aq[n], aa);
    store_q_row(&g_Bq[n], bb);

    float4 z = make_float4(0.f, 0.f, 0.f, 0.f);
    Gr[0] = z; Gr[1] = z; Gr[2] = z;
}

// =============================== edge kernel ================================
// Unsorted edge-parallel (R11, unchanged — control for the clock hypothesis).

__global__ void __launch_bounds__(256) edge_kernel(const int* __restrict__ es,
                                                   const int* __restrict__ ed,
                                                   const float* __restrict__ W1) {
    __shared__ float sW[HIDD * PADD];     // [10,10] padded to [10,12]
    for (int i = threadIdx.x; i < HIDD * PADD; i += blockDim.x) {
        int k = i / PADD, j = i % PADD;
        sW[i] = (j < HIDD) ? W1[k * HIDD + j] : 0.0f;
    }
    __syncthreads();

    int e = blockIdx.x * blockDim.x + threadIdx.x;
    if (e >= NE) return;

    int s = es[e];
    int d = ed[e];

    uint4 aq = __ldg(&g_Aq[d]);
    uint4 bq = __ldg(&g_Bq[s]);

    float av[10], bv[10];
    decode_q_row(aq, av);
    decode_q_row(bq, bv);

    float t[HIDD];
    #pragma unroll
    for (int i = 0; i < 10; i++) t[i] = fmaxf(av[i] + bv[i], 0.f);

    const float4* sW4 = (const float4*)sW;
    float4 u0 = make_float4(0.f,0.f,0.f,0.f);
    float4 u1 = make_float4(0.f,0.f,0.f,0.f);
    float4 u2 = make_float4(0.f,0.f,0.f,0.f);
    #pragma unroll
    for (int k = 0; k < HIDD; k++) {
        float tk = t[k];
        fma4(u0, tk, sW4[k * 3 + 0]);
        fma4(u1, tk, sW4[k * 3 + 1]);
        fma4(u2, tk, sW4[k * 3 + 2]);
    }

    u0.x = fmaxf(u0.x,0.f)*INV_MOD; u0.y = fmaxf(u0.y,0.f)*INV_MOD;
    u0.z = fmaxf(u0.z,0.f)*INV_MOD; u0.w = fmaxf(u0.w,0.f)*INV_MOD;
    u1.x = fmaxf(u1.x,0.f)*INV_MOD; u1.y = fmaxf(u1.y,0.f)*INV_MOD;
    u1.z = fmaxf(u1.z,0.f)*INV_MOD; u1.w = fmaxf(u1.w,0.f)*INV_MOD;
    u2.x = fmaxf(u2.x,0.f)*INV_MOD; u2.y = fmaxf(u2.y,0.f)*INV_MOD;

    float* Gr = g_agg + (long)d * PADD;   // 48B rows -> base 16B-aligned
    asm volatile("red.global.add.v4.f32 [%0], {%1, %2, %3, %4};"
                 :: "l"(Gr), "f"(u0.x), "f"(u0.y), "f"(u0.z), "f"(u0.w) : "memory");
    asm volatile("red.global.add.v4.f32 [%0], {%1, %2, %3, %4};"
                 :: "l"(Gr + 4), "f"(u1.x), "f"(u1.y), "f"(u1.z), "f"(u1.w) : "memory");
    asm volatile("red.global.add.v2.f32 [%0], {%1, %2};"
                 :: "l"(Gr + 8), "f"(u2.x), "f"(u2.y) : "memory");
}

// ============================ fused final head ==============================
// Block-tiled: 128 nodes/block. Phase A: all 256 threads (2 threads/node,
// 32 cols each) stage T k-major into smem. Phase B: register-tiled GEMM
// (4 nodes x 8 cols per thread, FFMA2).

__global__ void __launch_bounds__(256) final_fused(const float* __restrict__ Wf1,
                                                   const float* __restrict__ Wf2,
                                                   float* __restrict__ out) {
    __shared__ float sW1[HIDD * FEATD];   // 2.5 KB
    __shared__ float sW2[FEATD * FEATD];  // 16 KB, row-major [k][col]
    __shared__ float sT[FEATD * FB];      // 32 KB, k-major [k][node]
    for (int i = threadIdx.x; i < HIDD * FEATD; i += blockDim.x) sW1[i] = Wf1[i];
    for (int i = threadIdx.x; i < FEATD * FEATD; i += blockDim.x) sW2[i] = Wf2[i];
    __syncthreads();

    int n0 = blockIdx.x * FB;

    // ---- Phase A: 2 threads per node; each computes 32 of 64 T-columns ----
    {
        int nl   = threadIdx.x >> 1;          // 0..127 local node
        int half = threadIdx.x & 1;           // 0/1 -> cols [0,32) or [32,64)
        int n = n0 + nl;
        float h[HIDD];
        if (n < NN) {
            const float4* Gr = (const float4*)(g_agg + (long)n * PADD);
            float4 g0 = Gr[0], g1 = Gr[1], g2 = Gr[2];
            h[0]=fmaxf(g0.x,0.f); h[1]=fmaxf(g0.y,0.f); h[2]=fmaxf(g0.z,0.f); h[3]=fmaxf(g0.w,0.f);
            h[4]=fmaxf(g1.x,0.f); h[5]=fmaxf(g1.y,0.f); h[6]=fmaxf(g1.z,0.f); h[7]=fmaxf(g1.w,0.f);
            h[8]=fmaxf(g2.x,0.f); h[9]=fmaxf(g2.y,0.f);
        } else {
            #pragma unroll
            for (int i = 0; i < HIDD; i++) h[i] = 0.f;
        }

        const float4* sW1_4 = (const float4*)sW1;
        int cb = half * 8;                    // float4-column base (8 float4s = 32 cols)
        float4 t[8];
        #pragma unroll
        for (int c = 0; c < 8; c++) t[c] = make_float4(0.f,0.f,0.f,0.f);
        #pragma unroll
        for (int k = 0; k < HIDD; k++) {
            float hk = h[k];
            #pragma unroll
            for (int c = 0; c < 8; c++) fma4(t[c], hk, sW1_4[k * 16 + cb + c]);
        }
        // relu + transpose-store: sT[col][node]
        #pragma unroll
        for (int c = 0; c < 8; c++) {
            int col = half * 32 + 4 * c;
            sT[(col+0) * FB + nl] = fmaxf(t[c].x, 0.f);
            sT[(col+1) * FB + nl] = fmaxf(t[c].y, 0.f);
            sT[(col+2) * FB + nl] = fmaxf(t[c].z, 0.f);
            sT[(col+3) * FB + nl] = fmaxf(t[c].w, 0.f);
        }
    }
    __syncthreads();

    // ---- Phase B: 256 threads, each 4 nodes x 8 cols ----
    int ng = threadIdx.x >> 3;    // 0..31 node group
    int cg = threadIdx.x & 7;     // 0..7  col group
    int nl = ng * 4;
    int c0 = cg * 8;

    unsigned long long acc[4][4];  // [node][col-pair]
    #pragma unroll
    for (int j = 0; j < 4; j++)
        #pragma unroll
        for (int p = 0; p < 4; p++) acc[j][p] = pack2(0.f, 0.f);

    for (int k = 0; k < FEATD; k++) {
        float4 tn = *(const float4*)&sT[k * FB + nl];           // broadcast within 8 lanes
        const float4* wr = (const float4*)&sW2[k * FEATD + c0]; // 2 x LDS.128, conflict-free
        float4 wa = wr[0], wb = wr[1];
        unsigned long long w0 = pack2(wa.x, wa.y), w1 = pack2(wa.z, wa.w);
        unsigned long long w2 = pack2(wb.x, wb.y), w3 = pack2(wb.z, wb.w);
        float ts[4] = {tn.x, tn.y, tn.z, tn.w};
        #pragma unroll
        for (int j = 0; j < 4; j++) {
            unsigned long long tj = pack2(ts[j], ts[j]);
            ffma2(acc[j][0], tj, w0);
            ffma2(acc[j][1], tj, w1);
            ffma2(acc[j][2], tj, w2);
            ffma2(acc[j][3], tj, w3);
        }
    }

    #pragma unroll
    for (int j = 0; j < 4; j++) {
        int n = n0 + nl + j;
        if (n < NN) {
            float2 p0 = unpack2(acc[j][0]), p1 = unpack2(acc[j][1]);
            float2 p2 = unpack2(acc[j][2]), p3 = unpack2(acc[j][3]);
            float4 v0, v1;
            v0.x = fmaxf(p0.x, 0.f); v0.y = fmaxf(p0.y, 0.f);
            v0.z = fmaxf(p1.x, 0.f); v0.w = fmaxf(p1.y, 0.f);
            v1.x = fmaxf(p2.x, 0.f); v1.y = fmaxf(p2.y, 0.f);
            v1.z = fmaxf(p3.x, 0.f); v1.w = fmaxf(p3.y, 0.f);
            float4* orow = (float4*)(out + (long)n * FEATD + c0);
            orow[0] = v0;
            orow[1] = v1;
        }
    }
}

// ---------------------------------------------------------------------------
// Inputs (metadata order): X, W2_0, W1_0, W2_1, W1_1, W2_2, W1_2, Wf1, Wf2,
//                          edge_src (int32), edge_dst (int32)
// ---------------------------------------------------------------------------
extern "C" void kernel_launch(void* const* d_in, const int* in_sizes, int n_in,
                              void* d_out, int out_size) {
    const float* X    = (const float*)d_in[0];
    const float* W2_0 = (const float*)d_in[1];
    const float* W1_0 = (const float*)d_in[2];
    const float* W2_1 = (const float*)d_in[3];
    const float* W1_1 = (const float*)d_in[4];
    const float* W2_2 = (const float*)d_in[5];
    const float* W1_2 = (const float*)d_in[6];
    const float* Wf1  = (const float*)d_in[7];
    const float* Wf2  = (const float*)d_in[8];
    const int*   es   = (const int*)d_in[9];
    const int*   ed   = (const int*)d_in[10];
    float* out = (float*)d_out;

    const int nodeBlocks = (NN + 127) / 128;
    const int edgeBlocks = (NE + 255) / 256;
    const int finBlocks  = (NN + FB - 1) / FB;

    pre0<<<nodeBlocks, 128>>>(X, W2_0);
    edge_kernel<<<edgeBlocks, 256>>>(es, ed, W1_0);
    pre12<<<nodeBlocks, 128>>>(W2_1);
    edge_kernel<<<edgeBlocks, 256>>>(es, ed, W1_1);
    pre12<<<nodeBlocks, 128>>>(W2_2);
    edge_kernel<<<edgeBlocks, 256>>>(es, ed, W1_2);
    final_fused<<<finBlocks, 256>>>(Wf1, Wf2, out);
}